// round 7
// baseline (speedup 1.0000x reference)
#include <cuda_runtime.h>
#include <cuda_bf16.h>
#include <cstdint>

#define MAXN 100000
#define MAXE 1600000
#define F 64

#define SCAN_TPB 256
#define SCAN_EPT 8
#define SCAN_EPB (SCAN_TPB * SCAN_EPT)   // 2048
#define MAX_NB 1024

#define AS_STRIDE 68
#define WS_STRIDE 72
#define GEMM_SMEM ((2 * 64 * AS_STRIDE + 2 * 64 * WS_STRIDE) * 4)  // 71680 B

// -------- scratch (static device globals; no allocation allowed) ----------
__device__ float g_h1[(size_t)MAXN * F];
__device__ int   g_deg[MAXN];
__device__ int   g_rowstart[MAXN];
__device__ int   g_cursor[MAXN];
__device__ int   g_eidx[MAXE];
__device__ unsigned long long g_scanstate[MAX_NB];  // {flag:32 | value:32}
__device__ int   g_is64;

// --------------------- zero + edge dtype detection -------------------------
// Reference claims int64 edges, but JAX without x64 silently emits int32.
__global__ void k_zero_detect(const void* __restrict__ eiv, int n) {
    int i = blockIdx.x * blockDim.x + threadIdx.x;
    if (i < n) g_deg[i] = 0;
    if (i < MAX_NB) g_scanstate[i] = 0ULL;
    if (i == 0) {
        const long long* p = (const long long*)eiv;
        int ok = 1;
        #pragma unroll 1
        for (int j = 0; j < 64; j++) {
            long long v = p[j];
            if (v < 0 || v >= (long long)n) { ok = 0; break; }
        }
        g_is64 = ok;
    }
}

__device__ __forceinline__ int load_edge(const void* eiv, size_t idx, int n) {
    int v;
    if (g_is64) v = (int)((const long long*)eiv)[idx];
    else        v = ((const int*)eiv)[idx];
    return min(max(v, 0), n - 1);
}

// --------------------------- CSR build ------------------------------------
__global__ void k_count(const void* __restrict__ eiv, int E, int n) {
    int e = blockIdx.x * blockDim.x + threadIdx.x;
    if (e < E) {
        int d = load_edge(eiv, (size_t)E + e, n);
        atomicAdd(&g_deg[d], 1);
    }
}

// single-pass exclusive scan with decoupled lookback (nb <= 148 blocks,
// all co-resident -> spin is safe under graph capture)
__global__ void k_scan_one(int n) {
    __shared__ int wtot[SCAN_TPB / 32];
    __shared__ int s_off;
    int tid = threadIdx.x, b = blockIdx.x;
    int lane = tid & 31, wid = tid >> 5;
    int base = b * SCAN_EPB + tid * SCAN_EPT;
    int v[SCAN_EPT];
    int tot = 0;
    #pragma unroll
    for (int i = 0; i < SCAN_EPT; i++) {
        int id = base + i;
        int idc = id < n ? id : (n - 1);
        int val = g_deg[idc];
        v[i] = (id < n) ? val : 0;
        tot += v[i];
    }
    // warp inclusive scan of thread totals
    int incl = tot;
    #pragma unroll
    for (int off = 1; off < 32; off <<= 1) {
        int t = __shfl_up_sync(0xffffffffu, incl, off);
        if (lane >= off) incl += t;
    }
    if (lane == 31) wtot[wid] = incl;
    __syncthreads();
    if (tid < 32) {
        int w = (tid < SCAN_TPB / 32) ? wtot[tid] : 0;
        int wincl = w;
        #pragma unroll
        for (int off = 1; off < 32; off <<= 1) {
            int t = __shfl_up_sync(0xffffffffu, wincl, off);
            if (tid >= off) wincl += t;
        }
        if (tid < SCAN_TPB / 32) wtot[tid] = wincl - w;   // exclusive warp offsets
    }
    __syncthreads();
    int block_tot = wtot[SCAN_TPB / 32 - 1];
    // recompute block total: last warp offset + last warp's inclusive... simpler:
    // block_tot = sum of all (use warp 7 offset + its inclusive last). Compute via shared:
    // wtot[wid] is exclusive; block_tot = wtot[7] + (warp7 inclusive total). Instead reduce tot:
    // do a safe reduction:
    __shared__ int s_bt;
    if (tid == 0) s_bt = 0;
    __syncthreads();
    if (lane == 0) atomicAdd(&s_bt, 0);  // noop keep order
    // accumulate warp sums
    {
        int wsum = __shfl_sync(0xffffffffu, incl, 31);  // warp total
        if (lane == 0) atomicAdd(&s_bt, wsum);
    }
    __syncthreads();
    block_tot = s_bt;

    // publish + lookback (warp 0)
    if (tid < 32) {
        if (b == 0) {
            if (lane == 0) {
                atomicExch(&g_scanstate[0], (2ULL << 32) | (unsigned)block_tot);
                s_off = 0;
            }
        } else {
            if (lane == 0)
                atomicExch(&g_scanstate[b], (1ULL << 32) | (unsigned)block_tot);
            int running = 0;
            int p = b - 1;
            while (true) {
                int idx = p - lane;
                int flag, val;
                if (idx >= 0) {
                    unsigned long long s = atomicAdd(&g_scanstate[idx], 0ULL);
                    flag = (int)(s >> 32);
                    val  = (int)(unsigned)s;
                } else { flag = 2; val = 0; }
                if (!__all_sync(0xffffffffu, flag != 0)) continue;
                unsigned m2 = __ballot_sync(0xffffffffu, flag == 2);
                int contrib;
                if (m2 == 0) {
                    contrib = val;          // all aggregates: take whole window
                } else {
                    int stop = __ffs(m2) - 1;   // nearest predecessor with inclusive
                    contrib = (lane <= stop) ? val : 0;
                }
                #pragma unroll
                for (int off = 16; off > 0; off >>= 1)
                    contrib += __shfl_down_sync(0xffffffffu, contrib, off);
                contrib = __shfl_sync(0xffffffffu, contrib, 0);
                running += contrib;
                if (m2 != 0) break;
                p -= 32;
            }
            if (lane == 0) {
                atomicExch(&g_scanstate[b], (2ULL << 32) | (unsigned)(running + block_tot));
                s_off = running;
            }
        }
    }
    __syncthreads();
    int run = s_off + wtot[wid] + (incl - tot);
    #pragma unroll
    for (int i = 0; i < SCAN_EPT; i++) {
        int id = base + i;
        if (id < n) { g_rowstart[id] = run; g_cursor[id] = run; }
        run += v[i];
    }
}

__global__ void k_fill(const void* __restrict__ eiv, int E, int n) {
    int e = blockIdx.x * blockDim.x + threadIdx.x;
    if (e < E) {
        int d = load_edge(eiv, (size_t)E + e, n);
        int s = load_edge(eiv, (size_t)e, n);
        int pos = atomicAdd(&g_cursor[d], 1);
        if (pos < MAXE) g_eidx[pos] = s;
    }
}

// ------------------------ tensor-core fused layer --------------------------
__device__ __forceinline__ uint32_t f2tf32(float x) {
    uint32_t r;
    asm("cvt.rna.tf32.f32 %0, %1;" : "=r"(r) : "f"(x));
    return r;
}

__device__ __forceinline__ void mma_tf32(float* d,
    uint32_t a0, uint32_t a1, uint32_t a2, uint32_t a3,
    uint32_t b0, uint32_t b1)
{
    asm volatile(
        "mma.sync.aligned.m16n8k8.row.col.f32.tf32.tf32.f32 "
        "{%0,%1,%2,%3}, {%4,%5,%6,%7}, {%8,%9}, {%0,%1,%2,%3};"
        : "+f"(d[0]), "+f"(d[1]), "+f"(d[2]), "+f"(d[3])
        : "r"(a0), "r"(a1), "r"(a2), "r"(a3), "r"(b0), "r"(b1));
}

extern __shared__ uint32_t dyn_smem[];

// Fused mainloop for one SAGE layer on a 64-row tile:
//   acc = A[tile] @ W0 + mean_gather(A)[tile] @ W1     (3xTF32, fp32 accum)
// pass 0 loads A rows directly; pass 1 gathers+means neighbor rows of A
// (CSR in g_rowstart/g_deg/g_eidx), writing tf32 hi/lo splits to shared.
__device__ __forceinline__ void fused_mainloop(
    const float* __restrict__ A, const float* __restrict__ W0,
    const float* __restrict__ W1, int n, float acc[4][4])
{
    uint32_t* As_hi = dyn_smem;
    uint32_t* As_lo = As_hi + 64 * AS_STRIDE;
    uint32_t* Ws_hi = As_lo + 64 * AS_STRIDE;
    uint32_t* Ws_lo = Ws_hi + 64 * WS_STRIDE;

    int tid = threadIdx.x, lane = tid & 31, wid = tid >> 5;
    int row0 = blockIdx.x * 64;
    int rbase = (wid >> 1) * 16, nbase0 = (wid & 1) * 32;
    int g = lane >> 2, t = lane & 3;
    const float2* f2 = (const float2*)A;

    #pragma unroll
    for (int pass = 0; pass < 2; pass++) {
        __syncthreads();
        if (pass == 0) {
            // direct rows of A
            int r = tid >> 2, kc = (tid & 3) * 16;
            int gr = row0 + r;
            int grc = gr < n ? gr : (n - 1);
            const float4* a4 = (const float4*)(A + (size_t)grc * 64 + kc);
            #pragma unroll
            for (int i = 0; i < 4; i++) {
                float4 v = a4[i];
                float vv[4] = {v.x, v.y, v.z, v.w};
                #pragma unroll
                for (int j = 0; j < 4; j++) {
                    uint32_t hi = f2tf32(vv[j]);
                    float lo = vv[j] - __uint_as_float(hi);
                    As_hi[r * AS_STRIDE + kc + i * 4 + j] = hi;
                    As_lo[r * AS_STRIDE + kc + i * 4 + j] = f2tf32(lo);
                }
            }
        } else {
            // gather-mean: warp w handles rows w*8 .. w*8+7; lane owns float2
            #pragma unroll 1
            for (int q = 0; q < 8; q++) {
                int r = wid * 8 + q;
                int node = row0 + r;
                if (node >= n) node = n - 1;
                int s = g_rowstart[node];
                int d = g_deg[node];
                float2 av = make_float2(0.f, 0.f);
                int i = 0;
                for (; i + 3 < d; i += 4) {
                    int s0 = g_eidx[s + i];
                    int s1 = g_eidx[s + i + 1];
                    int s2 = g_eidx[s + i + 2];
                    int s3 = g_eidx[s + i + 3];
                    float2 a = f2[(size_t)s0 * 32 + lane];
                    float2 b = f2[(size_t)s1 * 32 + lane];
                    float2 c = f2[(size_t)s2 * 32 + lane];
                    float2 e = f2[(size_t)s3 * 32 + lane];
                    av.x += (a.x + b.x) + (c.x + e.x);
                    av.y += (a.y + b.y) + (c.y + e.y);
                }
                for (; i < d; i++) {
                    int s0 = g_eidx[s + i];
                    float2 a = f2[(size_t)s0 * 32 + lane];
                    av.x += a.x; av.y += a.y;
                }
                float inv = 1.0f / (float)max(d, 1);
                av.x *= inv; av.y *= inv;
                uint32_t hx = f2tf32(av.x);
                uint32_t hy = f2tf32(av.y);
                As_hi[r * AS_STRIDE + 2 * lane]     = hx;
                As_hi[r * AS_STRIDE + 2 * lane + 1] = hy;
                As_lo[r * AS_STRIDE + 2 * lane]     = f2tf32(av.x - __uint_as_float(hx));
                As_lo[r * AS_STRIDE + 2 * lane + 1] = f2tf32(av.y - __uint_as_float(hy));
            }
        }
        {
            const float* W = pass ? W1 : W0;
            int kk = tid >> 2, jc = (tid & 3) * 16;
            const float4* w4 = (const float4*)(W + kk * 64 + jc);
            #pragma unroll
            for (int i = 0; i < 4; i++) {
                float4 v = w4[i];
                float vv[4] = {v.x, v.y, v.z, v.w};
                #pragma unroll
                for (int j = 0; j < 4; j++) {
                    uint32_t hi = f2tf32(vv[j]);
                    float lo = vv[j] - __uint_as_float(hi);
                    Ws_hi[kk * WS_STRIDE + jc + i * 4 + j] = hi;
                    Ws_lo[kk * WS_STRIDE + jc + i * 4 + j] = f2tf32(lo);
                }
            }
        }
        __syncthreads();
        #pragma unroll
        for (int ks = 0; ks < 8; ks++) {
            int kk = ks * 8;
            int ra = (rbase + g) * AS_STRIDE + kk + t;
            int rb = (rbase + g + 8) * AS_STRIDE + kk + t;
            uint32_t ah0 = As_hi[ra], ah1 = As_hi[rb], ah2 = As_hi[ra + 4], ah3 = As_hi[rb + 4];
            uint32_t al0 = As_lo[ra], al1 = As_lo[rb], al2 = As_lo[ra + 4], al3 = As_lo[rb + 4];
            #pragma unroll
            for (int nt = 0; nt < 4; nt++) {
                int nb = nbase0 + nt * 8 + g;
                int i0 = (kk + t) * WS_STRIDE + nb;
                int i1 = (kk + t + 4) * WS_STRIDE + nb;
                uint32_t bh0 = Ws_hi[i0], bh1 = Ws_hi[i1];
                uint32_t bl0 = Ws_lo[i0], bl1 = Ws_lo[i1];
                mma_tf32(acc[nt], al0, al1, al2, al3, bh0, bh1);
                mma_tf32(acc[nt], ah0, ah1, ah2, ah3, bl0, bl1);
                mma_tf32(acc[nt], ah0, ah1, ah2, ah3, bh0, bh1);
            }
        }
    }
}

// layer 1: g_h1 = relu(x@W1_root + mean_agg(x)@W1_agg + b1)
__global__ void k_layer1(const float* __restrict__ A, const float* __restrict__ W0,
                         const float* __restrict__ W1, const float* __restrict__ bias, int n)
{
    float acc[4][4] = {};
    fused_mainloop(A, W0, W1, n, acc);

    int lane = threadIdx.x & 31, wid = threadIdx.x >> 5;
    int row0 = blockIdx.x * 64;
    int rbase = (wid >> 1) * 16, nbase0 = (wid & 1) * 32;
    int g = lane >> 2, t = lane & 3;
    #pragma unroll
    for (int nt = 0; nt < 4; nt++) {
        int col = nbase0 + nt * 8 + 2 * t;
        float b0v = bias[col], b1v = bias[col + 1];
        int r_top = row0 + rbase + g;
        if (r_top < n) {
            float2 o;
            o.x = fmaxf(acc[nt][0] + b0v, 0.f);
            o.y = fmaxf(acc[nt][1] + b1v, 0.f);
            *(float2*)(g_h1 + (size_t)r_top * 64 + col) = o;
        }
        int r_bot = r_top + 8;
        if (r_bot < n) {
            float2 o;
            o.x = fmaxf(acc[nt][2] + b0v, 0.f);
            o.y = fmaxf(acc[nt][3] + b1v, 0.f);
            *(float2*)(g_h1 + (size_t)r_bot * 64 + col) = o;
        }
    }
}

// layer 2 + fused 64->2 head
__global__ void k_layer2(const float* __restrict__ W0, const float* __restrict__ W1,
                         const float* __restrict__ bias,
                         const float* __restrict__ Wlin, const float* __restrict__ blin,
                         float* __restrict__ out, int n)
{
    __shared__ float Wls[128];
    __shared__ float bls[2];
    int tid = threadIdx.x;
    if (tid < 128) Wls[tid] = Wlin[tid];
    if (tid < 2)   bls[tid] = blin[tid];

    float acc[4][4] = {};
    fused_mainloop((const float*)g_h1, W0, W1, n, acc);

    int lane = tid & 31, wid = tid >> 5;
    int row0 = blockIdx.x * 64;
    int rbase = (wid >> 1) * 16, nbase0 = (wid & 1) * 32;
    int g = lane >> 2, t = lane & 3;

    float* Hs = (float*)dyn_smem;   // reuse As_hi region as Hs[64][AS_STRIDE]
    __syncthreads();                // all mma reads of shared done
    #pragma unroll
    for (int nt = 0; nt < 4; nt++) {
        int col = nbase0 + nt * 8 + 2 * t;
        float b0v = bias[col], b1v = bias[col + 1];
        int rt = rbase + g, rb = rt + 8;
        Hs[rt * AS_STRIDE + col]     = fmaxf(acc[nt][0] + b0v, 0.f);
        Hs[rt * AS_STRIDE + col + 1] = fmaxf(acc[nt][1] + b1v, 0.f);
        Hs[rb * AS_STRIDE + col]     = fmaxf(acc[nt][2] + b0v, 0.f);
        Hs[rb * AS_STRIDE + col + 1] = fmaxf(acc[nt][3] + b1v, 0.f);
    }
    __syncthreads();
    if (tid < 128) {
        int r = tid >> 1, j = tid & 1;
        int gr = row0 + r;
        if (gr < n) {
            float s = bls[j];
            #pragma unroll 8
            for (int c = 0; c < 64; c++)
                s += Hs[r * AS_STRIDE + c] * Wls[c * 2 + j];
            out[(size_t)gr * 2 + j] = s;
        }
    }
}

// ------------------------------ launch -------------------------------------
extern "C" void kernel_launch(void* const* d_in, const int* in_sizes, int n_in,
                              void* d_out, int out_size)
{
    const float* x      = (const float*)d_in[0];
    const void*  ei     = d_in[1];
    const float* W1_agg = (const float*)d_in[2];
    const float* W1_root= (const float*)d_in[3];
    const float* b1     = (const float*)d_in[4];
    const float* W2_agg = (const float*)d_in[5];
    const float* W2_root= (const float*)d_in[6];
    const float* b2     = (const float*)d_in[7];
    const float* W_lin  = (const float*)d_in[8];
    const float* b_lin  = (const float*)d_in[9];
    float*       out    = (float*)d_out;

    int n = in_sizes[0] / F;       // 100000
    int E = in_sizes[1] / 2;       // 1600000
    int nb = (n + SCAN_EPB - 1) / SCAN_EPB;   // 49 <= 148 (co-residency for lookback)

    static int attr_done = 0;
    if (!attr_done) {
        cudaFuncSetAttribute(k_layer1, cudaFuncAttributeMaxDynamicSharedMemorySize, GEMM_SMEM);
        cudaFuncSetAttribute(k_layer2, cudaFuncAttributeMaxDynamicSharedMemorySize, GEMM_SMEM);
        attr_done = 1;
    }

    // CSR build (reused by both layers)
    k_zero_detect<<<(n + 255) / 256, 256>>>(ei, n);
    k_count<<<(E + 255) / 256, 256>>>(ei, E, n);
    k_scan_one<<<nb, SCAN_TPB>>>(n);
    k_fill<<<(E + 255) / 256, 256>>>(ei, E, n);

    int gemm_blocks = (n + 63) / 64;
    k_layer1<<<gemm_blocks, 256, GEMM_SMEM>>>(x, W1_root, W1_agg, b1, n);
    k_layer2<<<gemm_blocks, 256, GEMM_SMEM>>>(W2_root, W2_agg, b2, W_lin, b_lin, out, n);
}

// round 8
// speedup vs baseline: 1.1583x; 1.1583x over previous
#include <cuda_runtime.h>
#include <cuda_bf16.h>
#include <cstdint>

#define MAXN 100000
#define MAXE 1600000
#define F 64

#define SCAN_TPB 256
#define SCAN_EPT 8
#define SCAN_EPB (SCAN_TPB * SCAN_EPT)   // 2048
#define MAX_NB 1024

#define AS_STRIDE 68
#define WS_STRIDE 72
#define GEMM_SMEM ((2 * 64 * AS_STRIDE + 2 * 64 * WS_STRIDE) * 4)  // 71680 B

// -------- scratch (static device globals; no allocation allowed) ----------
__device__ float g_agg[(size_t)MAXN * F];
__device__ float g_h1[(size_t)MAXN * F];
__device__ int   g_deg[MAXN];
__device__ int   g_rowstart[MAXN];
__device__ int   g_cursor[MAXN];
__device__ int   g_eidx[MAXE];
__device__ unsigned long long g_scanstate[MAX_NB];  // {flag:32 | value:32}
__device__ int   g_is64;

// --------------------- zero + edge dtype detection -------------------------
// Reference claims int64 edges, but JAX without x64 silently emits int32.
__global__ void k_zero_detect(const void* __restrict__ eiv, int n) {
    int i = blockIdx.x * blockDim.x + threadIdx.x;
    if (i < n) g_deg[i] = 0;
    if (i < MAX_NB) g_scanstate[i] = 0ULL;
    if (i == 0) {
        const long long* p = (const long long*)eiv;
        int ok = 1;
        #pragma unroll 1
        for (int j = 0; j < 64; j++) {
            long long v = p[j];
            if (v < 0 || v >= (long long)n) { ok = 0; break; }
        }
        g_is64 = ok;
    }
}

__device__ __forceinline__ int load_edge(const void* eiv, size_t idx, int n) {
    int v;
    if (g_is64) v = (int)((const long long*)eiv)[idx];
    else        v = ((const int*)eiv)[idx];
    return min(max(v, 0), n - 1);
}

// --------------------------- CSR build ------------------------------------
__global__ void k_count(const void* __restrict__ eiv, int E, int n) {
    int e = blockIdx.x * blockDim.x + threadIdx.x;
    if (e < E) {
        int d = load_edge(eiv, (size_t)E + e, n);
        atomicAdd(&g_deg[d], 1);
    }
}

// single-pass exclusive scan with decoupled lookback (nb <= 148 blocks,
// all co-resident -> spin is safe under graph capture)
__global__ void k_scan_one(int n) {
    __shared__ int wtot[SCAN_TPB / 32];
    __shared__ int s_off;
    __shared__ int s_bt;
    int tid = threadIdx.x, b = blockIdx.x;
    int lane = tid & 31, wid = tid >> 5;
    int base = b * SCAN_EPB + tid * SCAN_EPT;
    int v[SCAN_EPT];
    int tot = 0;
    #pragma unroll
    for (int i = 0; i < SCAN_EPT; i++) {
        int id = base + i;
        int idc = id < n ? id : (n - 1);
        int val = g_deg[idc];
        v[i] = (id < n) ? val : 0;
        tot += v[i];
    }
    // warp inclusive scan of thread totals
    int incl = tot;
    #pragma unroll
    for (int off = 1; off < 32; off <<= 1) {
        int t = __shfl_up_sync(0xffffffffu, incl, off);
        if (lane >= off) incl += t;
    }
    if (lane == 31) wtot[wid] = incl;
    if (tid == 0) s_bt = 0;
    __syncthreads();
    if (tid < 32) {
        int w = (tid < SCAN_TPB / 32) ? wtot[tid] : 0;
        int wincl = w;
        #pragma unroll
        for (int off = 1; off < 32; off <<= 1) {
            int t = __shfl_up_sync(0xffffffffu, wincl, off);
            if (tid >= off) wincl += t;
        }
        if (tid < SCAN_TPB / 32) wtot[tid] = wincl - w;   // exclusive warp offsets
        if (tid == SCAN_TPB / 32 - 1) s_bt = wincl;       // block total
    }
    __syncthreads();
    int block_tot = s_bt;

    // publish + lookback (warp 0)
    if (tid < 32) {
        if (b == 0) {
            if (lane == 0) {
                atomicExch(&g_scanstate[0], (2ULL << 32) | (unsigned)block_tot);
                s_off = 0;
            }
        } else {
            if (lane == 0)
                atomicExch(&g_scanstate[b], (1ULL << 32) | (unsigned)block_tot);
            int running = 0;
            int p = b - 1;
            while (true) {
                int idx = p - lane;
                int flag, val;
                if (idx >= 0) {
                    unsigned long long s = atomicAdd(&g_scanstate[idx], 0ULL);
                    flag = (int)(s >> 32);
                    val  = (int)(unsigned)s;
                } else { flag = 2; val = 0; }
                if (!__all_sync(0xffffffffu, flag != 0)) continue;
                unsigned m2 = __ballot_sync(0xffffffffu, flag == 2);
                int contrib;
                if (m2 == 0) {
                    contrib = val;              // whole window is aggregates
                } else {
                    int stop = __ffs(m2) - 1;   // nearest inclusive predecessor
                    contrib = (lane <= stop) ? val : 0;
                }
                #pragma unroll
                for (int off = 16; off > 0; off >>= 1)
                    contrib += __shfl_down_sync(0xffffffffu, contrib, off);
                contrib = __shfl_sync(0xffffffffu, contrib, 0);
                running += contrib;
                if (m2 != 0) break;
                p -= 32;
            }
            if (lane == 0) {
                atomicExch(&g_scanstate[b], (2ULL << 32) | (unsigned)(running + block_tot));
                s_off = running;
            }
        }
    }
    __syncthreads();
    int run = s_off + wtot[wid] + (incl - tot);
    #pragma unroll
    for (int i = 0; i < SCAN_EPT; i++) {
        int id = base + i;
        if (id < n) { g_rowstart[id] = run; g_cursor[id] = run; }
        run += v[i];
    }
}

__global__ void k_fill(const void* __restrict__ eiv, int E, int n) {
    int e = blockIdx.x * blockDim.x + threadIdx.x;
    if (e < E) {
        int d = load_edge(eiv, (size_t)E + e, n);
        int s = load_edge(eiv, (size_t)e, n);
        int pos = atomicAdd(&g_cursor[d], 1);
        if (pos < MAXE) g_eidx[pos] = s;
    }
}

// ------------------------ mean aggregation (gather-side) -------------------
// one warp per node; each lane owns one float2 (features 2*lane, 2*lane+1)
__device__ __forceinline__ void agg_body(const float* __restrict__ feat, int n) {
    int w = (blockIdx.x * blockDim.x + threadIdx.x) >> 5;
    int lane = threadIdx.x & 31;
    if (w >= n) return;
    int s = g_rowstart[w];
    int d = g_deg[w];
    float2 acc = make_float2(0.f, 0.f);
    const float2* f2 = (const float2*)feat;
    int i = 0;
    for (; i + 3 < d; i += 4) {
        int s0 = g_eidx[s + i];
        int s1 = g_eidx[s + i + 1];
        int s2 = g_eidx[s + i + 2];
        int s3 = g_eidx[s + i + 3];
        float2 a = f2[(size_t)s0 * 32 + lane];
        float2 b = f2[(size_t)s1 * 32 + lane];
        float2 c = f2[(size_t)s2 * 32 + lane];
        float2 e = f2[(size_t)s3 * 32 + lane];
        acc.x += (a.x + b.x) + (c.x + e.x);
        acc.y += (a.y + b.y) + (c.y + e.y);
    }
    for (; i < d; i++) {
        int s0 = g_eidx[s + i];
        float2 a = f2[(size_t)s0 * 32 + lane];
        acc.x += a.x; acc.y += a.y;
    }
    float inv = 1.0f / (float)max(d, 1);
    acc.x *= inv; acc.y *= inv;
    ((float2*)g_agg)[(size_t)w * 32 + lane] = acc;
}

__global__ void k_agg_x(const float* __restrict__ x, int n)  { agg_body(x, n); }
__global__ void k_agg_h1(int n)                              { agg_body(g_h1, n); }

// ------------------------ tensor-core GEMM (3xTF32) ------------------------
__device__ __forceinline__ uint32_t f2tf32(float x) {
    uint32_t r;
    asm("cvt.rna.tf32.f32 %0, %1;" : "=r"(r) : "f"(x));
    return r;
}

__device__ __forceinline__ void mma_tf32(float* d,
    uint32_t a0, uint32_t a1, uint32_t a2, uint32_t a3,
    uint32_t b0, uint32_t b1)
{
    asm volatile(
        "mma.sync.aligned.m16n8k8.row.col.f32.tf32.tf32.f32 "
        "{%0,%1,%2,%3}, {%4,%5,%6,%7}, {%8,%9}, {%0,%1,%2,%3};"
        : "+f"(d[0]), "+f"(d[1]), "+f"(d[2]), "+f"(d[3])
        : "r"(a0), "r"(a1), "r"(a2), "r"(a3), "r"(b0), "r"(b1));
}

extern __shared__ uint32_t dyn_smem[];

// Shared mainloop: acc[nt][4] = A0@W0 + g_agg@W1 for this block's 64-row tile.
// Warp layout: 8 warps -> 4 row-tiles(16) x 2 col-tiles(32); ntile = 4 x n8.
__device__ __forceinline__ void gemm_mainloop(
    const float* __restrict__ A0, const float* __restrict__ W0,
    const float* __restrict__ W1, int n, float acc[4][4])
{
    uint32_t* As_hi = dyn_smem;
    uint32_t* As_lo = As_hi + 64 * AS_STRIDE;
    uint32_t* Ws_hi = As_lo + 64 * AS_STRIDE;
    uint32_t* Ws_lo = Ws_hi + 64 * WS_STRIDE;

    int tid = threadIdx.x, lane = tid & 31, wid = tid >> 5;
    int row0 = blockIdx.x * 64;
    int rbase = (wid >> 1) * 16, nbase0 = (wid & 1) * 32;
    int g = lane >> 2, t = lane & 3;

    #pragma unroll
    for (int pass = 0; pass < 2; pass++) {
        const float* A = pass ? (const float*)g_agg : A0;
        const float* W = pass ? W1 : (const float*)W0;
        __syncthreads();
        {
            int r = tid >> 2, kc = (tid & 3) * 16;
            int gr = row0 + r;
            int grc = gr < n ? gr : (n - 1);
            const float4* a4 = (const float4*)(A + (size_t)grc * 64 + kc);
            #pragma unroll
            for (int i = 0; i < 4; i++) {
                float4 v = a4[i];
                float vv[4] = {v.x, v.y, v.z, v.w};
                #pragma unroll
                for (int j = 0; j < 4; j++) {
                    uint32_t hi = f2tf32(vv[j]);
                    float lo = vv[j] - __uint_as_float(hi);
                    As_hi[r * AS_STRIDE + kc + i * 4 + j] = hi;
                    As_lo[r * AS_STRIDE + kc + i * 4 + j] = f2tf32(lo);
                }
            }
            int kk = tid >> 2, jc = (tid & 3) * 16;
            const float4* w4 = (const float4*)(W + kk * 64 + jc);
            #pragma unroll
            for (int i = 0; i < 4; i++) {
                float4 v = w4[i];
                float vv[4] = {v.x, v.y, v.z, v.w};
                #pragma unroll
                for (int j = 0; j < 4; j++) {
                    uint32_t hi = f2tf32(vv[j]);
                    float lo = vv[j] - __uint_as_float(hi);
                    Ws_hi[kk * WS_STRIDE + jc + i * 4 + j] = hi;
                    Ws_lo[kk * WS_STRIDE + jc + i * 4 + j] = f2tf32(lo);
                }
            }
        }
        __syncthreads();
        #pragma unroll
        for (int ks = 0; ks < 8; ks++) {
            int kk = ks * 8;
            int ra = (rbase + g) * AS_STRIDE + kk + t;
            int rb = (rbase + g + 8) * AS_STRIDE + kk + t;
            uint32_t ah0 = As_hi[ra], ah1 = As_hi[rb], ah2 = As_hi[ra + 4], ah3 = As_hi[rb + 4];
            uint32_t al0 = As_lo[ra], al1 = As_lo[rb], al2 = As_lo[ra + 4], al3 = As_lo[rb + 4];
            #pragma unroll
            for (int nt = 0; nt < 4; nt++) {
                int nb = nbase0 + nt * 8 + g;
                int i0 = (kk + t) * WS_STRIDE + nb;
                int i1 = (kk + t + 4) * WS_STRIDE + nb;
                uint32_t bh0 = Ws_hi[i0], bh1 = Ws_hi[i1];
                uint32_t bl0 = Ws_lo[i0], bl1 = Ws_lo[i1];
                mma_tf32(acc[nt], al0, al1, al2, al3, bh0, bh1);
                mma_tf32(acc[nt], ah0, ah1, ah2, ah3, bl0, bl1);
                mma_tf32(acc[nt], ah0, ah1, ah2, ah3, bh0, bh1);
            }
        }
    }
}

// layer 1: h1 = relu(x@W1_root + agg@W1_agg + b1)
__global__ void k_gemm_tc(const float* __restrict__ A0, const float* __restrict__ W0,
                          const float* __restrict__ W1, const float* __restrict__ bias, int n)
{
    float acc[4][4] = {};
    gemm_mainloop(A0, W0, W1, n, acc);

    int lane = threadIdx.x & 31, wid = threadIdx.x >> 5;
    int row0 = blockIdx.x * 64;
    int rbase = (wid >> 1) * 16, nbase0 = (wid & 1) * 32;
    int g = lane >> 2, t = lane & 3;
    #pragma unroll
    for (int nt = 0; nt < 4; nt++) {
        int col = nbase0 + nt * 8 + 2 * t;
        float b0v = bias[col], b1v = bias[col + 1];
        int r_top = row0 + rbase + g;
        if (r_top < n) {
            float2 o;
            o.x = fmaxf(acc[nt][0] + b0v, 0.f);
            o.y = fmaxf(acc[nt][1] + b1v, 0.f);
            *(float2*)(g_h1 + (size_t)r_top * 64 + col) = o;
        }
        int r_bot = r_top + 8;
        if (r_bot < n) {
            float2 o;
            o.x = fmaxf(acc[nt][2] + b0v, 0.f);
            o.y = fmaxf(acc[nt][3] + b1v, 0.f);
            *(float2*)(g_h1 + (size_t)r_bot * 64 + col) = o;
        }
    }
}

// layer 2 + fused 64->2 head: out = relu(h1@W2_root + agg@W2_agg + b2) @ Wlin + blin
__global__ void k_gemm_tc_final(const float* __restrict__ W0, const float* __restrict__ W1,
                                const float* __restrict__ bias,
                                const float* __restrict__ Wlin, const float* __restrict__ blin,
                                float* __restrict__ out, int n)
{
    __shared__ float Wls[128];
    __shared__ float bls[2];
    int tid = threadIdx.x;
    if (tid < 128) Wls[tid] = Wlin[tid];
    if (tid < 2)   bls[tid] = blin[tid];

    float acc[4][4] = {};
    gemm_mainloop((const float*)g_h1, W0, W1, n, acc);

    int lane = tid & 31, wid = tid >> 5;
    int row0 = blockIdx.x * 64;
    int rbase = (wid >> 1) * 16, nbase0 = (wid & 1) * 32;
    int g = lane >> 2, t = lane & 3;

    float* Hs = (float*)dyn_smem;   // reuse As_hi region as Hs[64][AS_STRIDE]
    __syncthreads();                // all mma reads of shared done
    #pragma unroll
    for (int nt = 0; nt < 4; nt++) {
        int col = nbase0 + nt * 8 + 2 * t;
        float b0v = bias[col], b1v = bias[col + 1];
        int rt = rbase + g, rb = rt + 8;
        Hs[rt * AS_STRIDE + col]     = fmaxf(acc[nt][0] + b0v, 0.f);
        Hs[rt * AS_STRIDE + col + 1] = fmaxf(acc[nt][1] + b1v, 0.f);
        Hs[rb * AS_STRIDE + col]     = fmaxf(acc[nt][2] + b0v, 0.f);
        Hs[rb * AS_STRIDE + col + 1] = fmaxf(acc[nt][3] + b1v, 0.f);
    }
    __syncthreads();
    if (tid < 128) {
        int r = tid >> 1, j = tid & 1;
        int gr = row0 + r;
        if (gr < n) {
            float s = bls[j];
            #pragma unroll 8
            for (int c = 0; c < 64; c++)
                s += Hs[r * AS_STRIDE + c] * Wls[c * 2 + j];
            out[(size_t)gr * 2 + j] = s;
        }
    }
}

// ------------------------------ launch -------------------------------------
extern "C" void kernel_launch(void* const* d_in, const int* in_sizes, int n_in,
                              void* d_out, int out_size)
{
    const float* x      = (const float*)d_in[0];
    const void*  ei     = d_in[1];
    const float* W1_agg = (const float*)d_in[2];
    const float* W1_root= (const float*)d_in[3];
    const float* b1     = (const float*)d_in[4];
    const float* W2_agg = (const float*)d_in[5];
    const float* W2_root= (const float*)d_in[6];
    const float* b2     = (const float*)d_in[7];
    const float* W_lin  = (const float*)d_in[8];
    const float* b_lin  = (const float*)d_in[9];
    float*       out    = (float*)d_out;

    int n = in_sizes[0] / F;       // 100000
    int E = in_sizes[1] / 2;       // 1600000
    int nb = (n + SCAN_EPB - 1) / SCAN_EPB;   // 49 <= 148 (co-residency for lookback)

    static int attr_done = 0;
    if (!attr_done) {
        cudaFuncSetAttribute(k_gemm_tc, cudaFuncAttributeMaxDynamicSharedMemorySize, GEMM_SMEM);
        cudaFuncSetAttribute(k_gemm_tc_final, cudaFuncAttributeMaxDynamicSharedMemorySize, GEMM_SMEM);
        attr_done = 1;
    }

    // CSR build (reused by both layers)
    k_zero_detect<<<(n + 255) / 256, 256>>>(ei, n);
    k_count<<<(E + 255) / 256, 256>>>(ei, E, n);
    k_scan_one<<<nb, SCAN_TPB>>>(n);
    k_fill<<<(E + 255) / 256, 256>>>(ei, E, n);

    int agg_blocks = (n * 32 + 255) / 256;
    int gemm_blocks = (n + 63) / 64;

    // layer 1
    k_agg_x<<<agg_blocks, 256>>>(x, n);
    k_gemm_tc<<<gemm_blocks, 256, GEMM_SMEM>>>(x, W1_root, W1_agg, b1, n);
    // layer 2 + fused output head
    k_agg_h1<<<agg_blocks, 256>>>(n);
    k_gemm_tc_final<<<gemm_blocks, 256, GEMM_SMEM>>>(W2_root, W2_agg, b2, W_lin, b_lin, out, n);
}